// round 12
// baseline (speedup 1.0000x reference)
#include <cuda_runtime.h>
#include <cuda_fp16.h>
#include <cstdint>

#define Bn 32
#define Sn 512
#define En 256
#define Hn 8
#define HEn 2048
#define Mn 16384
#define BHn 256

typedef __half fp16;

// ---------------------------------------------------------------------------
// Scratch (device globals; allocation-free). Everything fp16.
// ---------------------------------------------------------------------------
__device__ __align__(16) fp16 g_qh[(size_t)Mn * En];
__device__ __align__(16) fp16 g_kh[(size_t)Mn * En];
__device__ __align__(16) fp16 g_vh[(size_t)Mn * En];
__device__ __align__(16) fp16 g_Wqh[(size_t)Hn * En * En];
__device__ __align__(16) fp16 g_Wkh[(size_t)Hn * En * En];
__device__ __align__(16) fp16 g_Wvh[(size_t)Hn * En * En];
__device__ __align__(16) fp16 g_Woh[(size_t)En * HEn];
__device__ __align__(16) fp16 g_Qh[(size_t)BHn * Sn * En];
__device__ __align__(16) fp16 g_Kh[(size_t)BHn * Sn * En];
__device__ __align__(16) fp16 g_Vth[(size_t)BHn * En * Sn];
__device__ __align__(16) fp16 g_Ch[(size_t)Mn * HEn];

// ---------------------------------------------------------------------------
// PTX helpers (arch-portable: ldmatrix + mma.sync + cp.async, sm_80+)
// ---------------------------------------------------------------------------
__device__ __forceinline__ uint32_t smem_u32(const void* p) {
    uint32_t a;
    asm("{ .reg .u64 t; cvta.to.shared.u64 t, %1; cvt.u32.u64 %0, t; }"
        : "=r"(a) : "l"(p));
    return a;
}
__device__ __forceinline__ void ldsm_x4(uint32_t* r, uint32_t a) {
    asm volatile("ldmatrix.sync.aligned.m8n8.x4.shared.b16 {%0,%1,%2,%3}, [%4];"
                 : "=r"(r[0]), "=r"(r[1]), "=r"(r[2]), "=r"(r[3]) : "r"(a));
}
__device__ __forceinline__ void ldsm_x2(uint32_t* r, uint32_t a) {
    asm volatile("ldmatrix.sync.aligned.m8n8.x2.shared.b16 {%0,%1}, [%2];"
                 : "=r"(r[0]), "=r"(r[1]) : "r"(a));
}
__device__ __forceinline__ void mma_f16(float* c, const uint32_t* a,
                                        const uint32_t* b) {
    asm volatile(
        "mma.sync.aligned.m16n8k16.row.col.f32.f16.f16.f32 "
        "{%0,%1,%2,%3}, {%4,%5,%6,%7}, {%8,%9}, {%0,%1,%2,%3};"
        : "+f"(c[0]), "+f"(c[1]), "+f"(c[2]), "+f"(c[3])
        : "r"(a[0]), "r"(a[1]), "r"(a[2]), "r"(a[3]), "r"(b[0]), "r"(b[1]));
}
__device__ __forceinline__ void cp16(uint32_t s, const void* g) {
    asm volatile("cp.async.cg.shared.global [%0], [%1], 16;" :: "r"(s), "l"(g));
}
#define CP_COMMIT() asm volatile("cp.async.commit_group;" ::: "memory")
#define CP_WAIT1()  asm volatile("cp.async.wait_group 1;"  ::: "memory")

__device__ __forceinline__ uint32_t pack_h(float x, float y) {
    __half2 h = __floats2half2_rn(x, y);
    return *reinterpret_cast<uint32_t*>(&h);
}
__device__ __forceinline__ uint32_t swz(int row, int ch) {
    return (uint32_t)(((ch & ~7) | ((ch ^ row) & 7)) << 4);
}

// GEMM smem: 128 rows x 128B tiles, XOR-16B swizzle, A|B per stage, 3 stages
#define TILEB  16384
#define STAGEB (2 * TILEB)
#define NSTAGE 3
#define SM_SMEM (NSTAGE * STAGEB)   // 98304/CTA; 2 CTAs/SM

// Fused-attention smem: Q 32KB @0, S/P 64KB @32768, KV 3x32KB @98304
#define FA_SOFF 32768
#define FA_KVOFF 98304
#define FA_SMEM 196608

// ---------------------------------------------------------------------------
// Batched fp32 -> fp16 conversions (y selects tensor)
// ---------------------------------------------------------------------------
__global__ __launch_bounds__(256)
void cvt3_hi(const float* __restrict__ s0, const float* __restrict__ s1,
             const float* __restrict__ s2, fp16* __restrict__ d0,
             fp16* __restrict__ d1, fp16* __restrict__ d2, int n4)
{
    int i = blockIdx.x * blockDim.x + threadIdx.x;
    if (i >= n4) return;
    const float* s = (blockIdx.y == 0) ? s0 : (blockIdx.y == 1) ? s1 : s2;
    fp16* d = (blockIdx.y == 0) ? d0 : (blockIdx.y == 1) ? d1 : d2;
    float4 v = reinterpret_cast<const float4*>(s)[i];
    reinterpret_cast<uint2*>(d)[i] = make_uint2(pack_h(v.x, v.y), pack_h(v.z, v.w));
}
__global__ __launch_bounds__(256)
void cvt4_hi(const float* __restrict__ s0, const float* __restrict__ s1,
             const float* __restrict__ s2, const float* __restrict__ s3,
             fp16* __restrict__ d0, fp16* __restrict__ d1,
             fp16* __restrict__ d2, fp16* __restrict__ d3, int n4)
{
    int i = blockIdx.x * blockDim.x + threadIdx.x;
    if (i >= n4) return;
    const float* s = (blockIdx.y == 0) ? s0 : (blockIdx.y == 1) ? s1
                   : (blockIdx.y == 2) ? s2 : s3;
    fp16* d = (blockIdx.y == 0) ? d0 : (blockIdx.y == 1) ? d1
            : (blockIdx.y == 2) ? d2 : d3;
    float4 v = reinterpret_cast<const float4*>(s)[i];
    reinterpret_cast<uint2*>(d)[i] = make_uint2(pack_h(v.x, v.y), pack_h(v.z, v.w));
}

// ---------------------------------------------------------------------------
// Single-pass fp16 HMMA NT GEMM (projections + output projection), as R11.
// MODE 0: merged QKV projection (z=pp*8+h); MODE 4: outproj + bias.
// ---------------------------------------------------------------------------
template <int MODE>
__global__ __launch_bounds__(256, 2)
void gemm_hf(const fp16* __restrict__ A0, const fp16* __restrict__ A1,
             const fp16* __restrict__ A2, const fp16* __restrict__ B0,
             const fp16* __restrict__ B1, const fp16* __restrict__ B2,
             void* __restrict__ O0, void* __restrict__ O1,
             void* __restrict__ O2,
             const float* __restrict__ pad, const float* __restrict__ bias)
{
    extern __shared__ char smem[];
    const uint32_t sb = smem_u32(smem);
    const int tid = threadIdx.x, wid = tid >> 5, lane = tid & 31;
    const int z = blockIdx.z;
    const int m0 = blockIdx.y * 128, n0 = blockIdx.x * 128;

    int pp = 0, hh = 0;
    const fp16 *Ah, *Bh;
    int lda, ldb, nc;
    if constexpr (MODE == 0) {
        pp = z >> 3; hh = z & 7;
        const fp16* Ab = (pp == 0) ? A0 : (pp == 1) ? A1 : A2;
        const fp16* Bb = (pp == 0) ? B0 : (pp == 1) ? B1 : B2;
        Ah = Ab + (size_t)m0 * En;
        Bh = Bb + (size_t)hh * En * En + (size_t)n0 * En;
        lda = En; ldb = En; nc = En / 64;
    } else {
        Ah = A0 + (size_t)m0 * HEn;
        Bh = B0 + (size_t)n0 * HEn;
        lda = HEn; ldb = HEn; nc = HEn / 64;
    }

    auto issue = [&](int cc) {
        const uint32_t st = sb + (uint32_t)(cc % NSTAGE) * STAGEB;
        #pragma unroll
        for (int i = 0; i < 4; i++) {
            const int idx = i * 256 + tid;
            const int row = idx >> 3, ch = idx & 7;
            const uint32_t so = (uint32_t)((row << 7)) + swz(row, ch);
            const size_t ga = (size_t)row * lda + (size_t)cc * 64 + ch * 8;
            const size_t gb = (size_t)row * ldb + (size_t)cc * 64 + ch * 8;
            cp16(st + so, Ah + ga);
            cp16(st + TILEB + so, Bh + gb);
        }
    };

    issue(0); CP_COMMIT();
    issue(1); CP_COMMIT();

    const int wm = wid & 3, wn = wid >> 2;
    const int arow = wm * 32 + (lane & 15);
    const int ac   = lane >> 4;
    const int brow = wn * 64 + (lane & 7);
    const int bc   = (lane >> 3) & 1;

    float c[2][8][4] = {};

    for (int cc = 0; cc < nc; ++cc) {
        CP_WAIT1();
        __syncthreads();
        if (cc + 2 < nc) issue(cc + 2);
        CP_COMMIT();

        const uint32_t st = sb + (uint32_t)(cc % NSTAGE) * STAGEB;
        #pragma unroll
        for (int kb = 0; kb < 4; kb++) {
            uint32_t ah[2][4], bh[8][2];
            #pragma unroll
            for (int ma = 0; ma < 2; ma++)
                ldsm_x4(ah[ma], st + (uint32_t)((arow + ma * 16) << 7)
                                   + swz(arow, kb * 2 + ac));
            #pragma unroll
            for (int na = 0; na < 8; na++)
                ldsm_x2(bh[na], st + TILEB + (uint32_t)((brow + na * 8) << 7)
                                   + swz(brow, kb * 2 + bc));
            #pragma unroll
            for (int ma = 0; ma < 2; ma++)
                #pragma unroll
                for (int na = 0; na < 8; na++)
                    mma_f16(c[ma][na], ah[ma], bh[na]);
        }
    }

    const int g = lane >> 2, tig = lane & 3;

    if (MODE == 0 && pp == 2) {
        float* ts = reinterpret_cast<float*>(smem);
        __syncthreads();
        #pragma unroll
        for (int ma = 0; ma < 2; ma++) {
            const int rl = wm * 32 + ma * 16 + g;
            #pragma unroll
            for (int na = 0; na < 8; na++) {
                const int cl = wn * 64 + na * 8 + 2 * tig;
                ts[rl * 132 + cl]           = c[ma][na][0];
                ts[rl * 132 + cl + 1]       = c[ma][na][1];
                ts[(rl + 8) * 132 + cl]     = c[ma][na][2];
                ts[(rl + 8) * 132 + cl + 1] = c[ma][na][3];
            }
        }
        __syncthreads();
        fp16* Oh = (fp16*)O2;
        const int bb = m0 >> 9, sbase = m0 & 511;
        for (int i = tid; i < 128 * 64; i += 256) {
            const int d = i >> 6, s2 = (i & 63) * 2;
            float v0 = ts[s2 * 132 + d], v1 = ts[(s2 + 1) * 132 + d];
            size_t o = (((size_t)(bb * Hn + hh)) * En + n0 + d) * Sn + sbase + s2;
            *reinterpret_cast<uint32_t*>(Oh + o) = pack_h(v0, v1);
        }
        return;
    }

    #pragma unroll
    for (int ma = 0; ma < 2; ma++) {
        const int r0 = m0 + wm * 32 + ma * 16 + g;
        const int r1 = r0 + 8;
        float s0 = 1.0f, s1 = 1.0f;
        if constexpr (MODE == 0) {
            if (pp == 1) { s0 = pad[r0]; s1 = pad[r1]; }
        }
        #pragma unroll
        for (int na = 0; na < 8; na++) {
            const int cb = n0 + wn * 64 + na * 8 + 2 * tig;
            const float v0 = c[ma][na][0], v1 = c[ma][na][1];
            const float v2 = c[ma][na][2], v3 = c[ma][na][3];
            if constexpr (MODE == 0) {
                fp16* Oh = (fp16*)((pp == 0) ? O0 : O1);
                size_t o0 = (((size_t)((r0 >> 9) * Hn + hh)) * Sn + (r0 & 511)) * En + cb;
                size_t o1 = (((size_t)((r1 >> 9) * Hn + hh)) * Sn + (r1 & 511)) * En + cb;
                *reinterpret_cast<uint32_t*>(Oh + o0) = pack_h(v0 * s0, v1 * s0);
                *reinterpret_cast<uint32_t*>(Oh + o1) = pack_h(v2 * s1, v3 * s1);
            } else {
                float* O = (float*)O0;
                const float bx = bias[cb], by = bias[cb + 1];
                float* p0 = O + (size_t)r0 * En + cb;
                float* p1 = O + (size_t)r1 * En + cb;
                *reinterpret_cast<float2*>(p0) = make_float2(v0 + bx, v1 + by);
                *reinterpret_cast<float2*>(p1) = make_float2(v2 + bx, v3 + by);
            }
        }
    }
}

// ---------------------------------------------------------------------------
// Fused attention: scores + causal softmax + attn@V, one CTA per (q-tile, bh).
// Q tile 64x256 resident; K/V streamed in 64-wide chunks (3-stage cp.async);
// S/P tile 64x512 fp16 in smem (never touches DRAM).
// ---------------------------------------------------------------------------
__global__ __launch_bounds__(256, 1)
void attn_fused(const fp16* __restrict__ Qh, const fp16* __restrict__ Kh,
                const fp16* __restrict__ Vth, fp16* __restrict__ Ch)
{
    extern __shared__ char smem[];
    const uint32_t sb = smem_u32(smem);
    const int tid = threadIdx.x, wid = tid >> 5, lane = tid & 31;
    const int t = blockIdx.x;          // q-tile (64 rows), 0..7
    const int z = blockIdx.y;          // bh
    const int q0 = t * 64;

    const fp16* Qg = Qh  + (size_t)z * Sn * En + (size_t)q0 * En;
    const fp16* Kg = Kh  + (size_t)z * Sn * En;
    const fp16* Vg = Vth + (size_t)z * En * Sn;

    const int wm = wid & 3, wn = wid >> 2;

    // ---- prologue: Q tile (group 0), K0, K1 ----
    #pragma unroll
    for (int i = 0; i < 8; i++) {
        int idx = i * 256 + tid, row = idx >> 5, ch = idx & 31;
        cp16(sb + (uint32_t)(row << 9) + swz(row, ch),
             Qg + (size_t)row * En + ch * 8);
    }
    CP_COMMIT();

    auto loadK = [&](int j) {
        const uint32_t st = sb + FA_KVOFF + (uint32_t)(j % 3) * 32768;
        #pragma unroll
        for (int i = 0; i < 8; i++) {
            int idx = i * 256 + tid, row = idx >> 5, ch = idx & 31;
            cp16(st + (uint32_t)(row << 9) + swz(row, ch),
                 Kg + (size_t)(j * 64 + row) * En + ch * 8);
        }
    };
    auto loadV = [&](int j) {
        const uint32_t st = sb + FA_KVOFF + (uint32_t)(j % 3) * 32768;
        #pragma unroll
        for (int i = 0; i < 8; i++) {
            int idx = i * 256 + tid, row = idx >> 3, ch = idx & 7;
            cp16(st + (uint32_t)(row << 7) + swz(row, ch),
                 Vg + (size_t)row * Sn + j * 64 + ch * 8);
        }
    };

    loadK(0); CP_COMMIT();
    if (t >= 1) loadK(1);
    CP_COMMIT();

    const int arow    = wm * 16 + (lane & 15);
    const int ac      = lane >> 4;
    const int brow32  = wn * 32 + (lane & 7);
    const int brow128 = wn * 128 + (lane & 7);
    const int bc      = (lane >> 3) & 1;
    const int g = lane >> 2, tig = lane & 3;
    const float NEGINF = __int_as_float(0xff800000);

    // ---- phase 1: S_j = Q K_j^T / 16 (+causal) -> smem fp16 ----
    for (int j = 0; j <= t; j++) {
        CP_WAIT1();
        __syncthreads();
        if (j + 2 <= t) loadK(j + 2);
        CP_COMMIT();

        const uint32_t kst = sb + FA_KVOFF + (uint32_t)(j % 3) * 32768;
        float c[4][4] = {};
        #pragma unroll
        for (int s = 0; s < 16; s++) {
            uint32_t a[4], b[4][2];
            ldsm_x4(a, sb + (uint32_t)(arow << 9) + swz(arow, s * 2 + ac));
            #pragma unroll
            for (int na = 0; na < 4; na++)
                ldsm_x2(b[na], kst + (uint32_t)((brow32 + na * 8) << 9)
                                  + swz(brow32 + na * 8, s * 2 + bc));
            #pragma unroll
            for (int na = 0; na < 4; na++)
                mma_f16(c[na], a, b[na]);
        }
        #pragma unroll
        for (int na = 0; na < 4; na++) {
            const int col = wn * 32 + na * 8 + 2 * tig;
            const int ch = j * 8 + (col >> 3);
            #pragma unroll
            for (int h = 0; h < 2; h++) {
                const int rg = wm * 16 + g + h * 8;
                float v0 = c[na][h * 2]     * 0.0625f;
                float v1 = c[na][h * 2 + 1] * 0.0625f;
                if (j == t) {
                    if (col > rg)     v0 = NEGINF;
                    if (col + 1 > rg) v1 = NEGINF;
                }
                uint32_t off = FA_SOFF + (uint32_t)(rg << 10) + swz(rg, ch)
                             + (uint32_t)((col & 7) << 1);
                *reinterpret_cast<uint32_t*>(smem + off) = pack_h(v0, v1);
            }
        }
    }

    __syncthreads();                 // S complete; K reads complete

    // overlap V(0), V(1) loads with in-smem softmax
    loadV(0); CP_COMMIT();
    if (t >= 1) loadV(1);
    CP_COMMIT();

    // ---- phase 2: row softmax in smem (warp owns 8 rows) ----
    {
        const int cv = (t + 1) * 8;  // valid 16B chunks per row
        for (int rr = 0; rr < 8; rr++) {
            const int r = wid * 8 + rr;
            char* rowp = smem + FA_SOFF + (r << 10);
            const int ch0 = lane, ch1 = lane + 32;
            const bool k0v = ch0 < cv, k1v = ch1 < cv;
            float f0[8], f1[8];
            float m = -1e30f;
            if (k0v) {
                uint4 x = *reinterpret_cast<uint4*>(rowp + swz(r, ch0));
                const __half2* hp = reinterpret_cast<const __half2*>(&x);
                #pragma unroll
                for (int i = 0; i < 4; i++) {
                    float2 f = __half22float2(hp[i]);
                    f0[i * 2] = f.x; f0[i * 2 + 1] = f.y;
                    m = fmaxf(m, fmaxf(f.x, f.y));
                }
            }
            if (k1v) {
                uint4 x = *reinterpret_cast<uint4*>(rowp + swz(r, ch1));
                const __half2* hp = reinterpret_cast<const __half2*>(&x);
                #pragma unroll
                for (int i = 0; i < 4; i++) {
                    float2 f = __half22float2(hp[i]);
                    f1[i * 2] = f.x; f1[i * 2 + 1] = f.y;
                    m = fmaxf(m, fmaxf(f.x, f.y));
                }
            }
            #pragma unroll
            for (int o = 16; o; o >>= 1)
                m = fmaxf(m, __shfl_xor_sync(0xffffffffu, m, o));

            float s = 0.0f;
            if (k0v) {
                #pragma unroll
                for (int i = 0; i < 8; i++) { f0[i] = __expf(f0[i] - m); s += f0[i]; }
            }
            if (k1v) {
                #pragma unroll
                for (int i = 0; i < 8; i++) { f1[i] = __expf(f1[i] - m); s += f1[i]; }
            }
            #pragma unroll
            for (int o = 16; o; o >>= 1) s += __shfl_xor_sync(0xffffffffu, s, o);
            const float inv = 1.0f / s;

            if (k0v) {
                uint4 y;
                uint32_t* yp = reinterpret_cast<uint32_t*>(&y);
                #pragma unroll
                for (int i = 0; i < 4; i++)
                    yp[i] = pack_h(f0[i * 2] * inv, f0[i * 2 + 1] * inv);
                *reinterpret_cast<uint4*>(rowp + swz(r, ch0)) = y;
            }
            if (k1v) {
                uint4 y;
                uint32_t* yp = reinterpret_cast<uint32_t*>(&y);
                #pragma unroll
                for (int i = 0; i < 4; i++)
                    yp[i] = pack_h(f1[i * 2] * inv, f1[i * 2 + 1] * inv);
                *reinterpret_cast<uint4*>(rowp + swz(r, ch1)) = y;
            }
        }
    }
    __syncthreads();                 // P visible to all warps

    // ---- phase 3: O += P_j V_j ----
    float co[16][4] = {};
    for (int j = 0; j <= t; j++) {
        CP_WAIT1();
        __syncthreads();
        if (j + 2 <= t) loadV(j + 2);
        CP_COMMIT();

        const uint32_t vst = sb + FA_KVOFF + (uint32_t)(j % 3) * 32768;
        #pragma unroll
        for (int s = 0; s < 4; s++) {
            uint32_t a[4], b[16][2];
            ldsm_x4(a, sb + FA_SOFF + (uint32_t)(arow << 10)
                       + swz(arow, j * 8 + s * 2 + ac));
            #pragma unroll
            for (int na = 0; na < 16; na++)
                ldsm_x2(b[na], vst + (uint32_t)((brow128 + na * 8) << 7)
                                  + swz(brow128 + na * 8, s * 2 + bc));
            #pragma unroll
            for (int na = 0; na < 16; na++)
                mma_f16(co[na], a, b[na]);
        }
    }

    // ---- epilogue: O -> concat fp16 [B,S,H*E] ----
    const int bb = z >> 3, hh = z & 7;
    #pragma unroll
    for (int na = 0; na < 16; na++) {
        const int col = wn * 128 + na * 8 + 2 * tig;
        #pragma unroll
        for (int h = 0; h < 2; h++) {
            const int rq = q0 + wm * 16 + g + h * 8;
            size_t o = ((size_t)(bb * Sn + rq)) * HEn + hh * En + col;
            *reinterpret_cast<uint32_t*>(Ch + o) = pack_h(co[na][h * 2], co[na][h * 2 + 1]);
        }
    }
}

// ---------------------------------------------------------------------------
// Launch (my index 3 = attn_fused — the launch ncu profiles)
// ---------------------------------------------------------------------------
extern "C" void kernel_launch(void* const* d_in, const int* in_sizes, int n_in,
                              void* d_out, int out_size)
{
    const float* q   = (const float*)d_in[0];
    const float* k   = (const float*)d_in[1];
    const float* v   = (const float*)d_in[2];
    const float* pad = (const float*)d_in[3];
    // d_in[4] = attn_mask (causal applied analytically)
    const float* Wq  = (const float*)d_in[5];
    const float* Wk  = (const float*)d_in[6];
    const float* Wv  = (const float*)d_in[7];
    const float* Wo  = (const float*)d_in[8];
    const float* bo  = (const float*)d_in[9];
    float* out = (float*)d_out;

    fp16 *qh, *kh, *vh, *Wqh, *Wkh, *Wvh, *Woh;
    fp16 *Qh, *Kh, *Vth, *Ch;
    cudaGetSymbolAddress((void**)&qh,  g_qh);
    cudaGetSymbolAddress((void**)&kh,  g_kh);
    cudaGetSymbolAddress((void**)&vh,  g_vh);
    cudaGetSymbolAddress((void**)&Wqh, g_Wqh);
    cudaGetSymbolAddress((void**)&Wkh, g_Wkh);
    cudaGetSymbolAddress((void**)&Wvh, g_Wvh);
    cudaGetSymbolAddress((void**)&Woh, g_Woh);
    cudaGetSymbolAddress((void**)&Qh,  g_Qh);
    cudaGetSymbolAddress((void**)&Kh,  g_Kh);
    cudaGetSymbolAddress((void**)&Vth, g_Vth);
    cudaGetSymbolAddress((void**)&Ch,  g_Ch);

    cudaFuncSetAttribute((const void*)gemm_hf<0>, cudaFuncAttributeMaxDynamicSharedMemorySize, SM_SMEM);
    cudaFuncSetAttribute((const void*)gemm_hf<4>, cudaFuncAttributeMaxDynamicSharedMemorySize, SM_SMEM);
    cudaFuncSetAttribute((const void*)attn_fused, cudaFuncAttributeMaxDynamicSharedMemorySize, FA_SMEM);

    const int n4x = Mn * En / 4;          // 1048576
    const int n4w = Hn * En * En / 4;     // 131072 (== En*HEn/4 for Wo)

    // index 0-1: batched conversions
    cvt3_hi<<<dim3(n4x / 256, 3), 256>>>(q, k, v, qh, kh, vh, n4x);
    cvt4_hi<<<dim3(n4w / 256, 4), 256>>>(Wq, Wk, Wv, Wo, Wqh, Wkh, Wvh, Woh, n4w);

    // index 2: merged QKV projections, grid (2,128,24)
    gemm_hf<0><<<dim3(2, 128, 24), 256, SM_SMEM>>>(
        qh, kh, vh, Wqh, Wkh, Wvh, Qh, Kh, Vth, pad, nullptr);

    // index 3 (profiled): fused scores+softmax+attnV, grid (8 q-tiles, 256 bh)
    attn_fused<<<dim3(8, 256), 256, FA_SMEM>>>(Qh, Kh, Vth, Ch);

    // out projection: (2,128)
    gemm_hf<4><<<dim3(2, 128, 1), 256, SM_SMEM>>>(
        Ch, nullptr, nullptr, Woh, nullptr, nullptr, out, nullptr, nullptr,
        nullptr, bo);
}

// round 13
// speedup vs baseline: 1.0991x; 1.0991x over previous
#include <cuda_runtime.h>
#include <cuda_fp16.h>
#include <cstdint>

#define Bn 32
#define Sn 512
#define En 256
#define Hn 8
#define HEn 2048
#define Mn 16384
#define BHn 256

typedef __half fp16;

// ---------------------------------------------------------------------------
// Scratch (device globals; allocation-free). Everything fp16; scores are
// written fp16 directly into g_Ph and softmaxed in place.
// ---------------------------------------------------------------------------
__device__ __align__(16) fp16 g_qh[(size_t)Mn * En];
__device__ __align__(16) fp16 g_kh[(size_t)Mn * En];
__device__ __align__(16) fp16 g_vh[(size_t)Mn * En];
__device__ __align__(16) fp16 g_Wqh[(size_t)Hn * En * En];
__device__ __align__(16) fp16 g_Wkh[(size_t)Hn * En * En];
__device__ __align__(16) fp16 g_Wvh[(size_t)Hn * En * En];
__device__ __align__(16) fp16 g_Woh[(size_t)En * HEn];
__device__ __align__(16) fp16 g_Qh[(size_t)BHn * Sn * En];
__device__ __align__(16) fp16 g_Kh[(size_t)BHn * Sn * En];
__device__ __align__(16) fp16 g_Vth[(size_t)BHn * En * Sn];
__device__ __align__(16) fp16 g_Ph[(size_t)BHn * Sn * Sn];   // S then P (in place)
__device__ __align__(16) fp16 g_Ch[(size_t)Mn * HEn];

// ---------------------------------------------------------------------------
// PTX helpers (arch-portable: ldmatrix + mma.sync + cp.async, sm_80+)
// ---------------------------------------------------------------------------
__device__ __forceinline__ uint32_t smem_u32(const void* p) {
    uint32_t a;
    asm("{ .reg .u64 t; cvta.to.shared.u64 t, %1; cvt.u32.u64 %0, t; }"
        : "=r"(a) : "l"(p));
    return a;
}
__device__ __forceinline__ void ldsm_x4(uint32_t* r, uint32_t a) {
    asm volatile("ldmatrix.sync.aligned.m8n8.x4.shared.b16 {%0,%1,%2,%3}, [%4];"
                 : "=r"(r[0]), "=r"(r[1]), "=r"(r[2]), "=r"(r[3]) : "r"(a));
}
__device__ __forceinline__ void ldsm_x2(uint32_t* r, uint32_t a) {
    asm volatile("ldmatrix.sync.aligned.m8n8.x2.shared.b16 {%0,%1}, [%2];"
                 : "=r"(r[0]), "=r"(r[1]) : "r"(a));
}
__device__ __forceinline__ void mma_f16(float* c, const uint32_t* a,
                                        const uint32_t* b) {
    asm volatile(
        "mma.sync.aligned.m16n8k16.row.col.f32.f16.f16.f32 "
        "{%0,%1,%2,%3}, {%4,%5,%6,%7}, {%8,%9}, {%0,%1,%2,%3};"
        : "+f"(c[0]), "+f"(c[1]), "+f"(c[2]), "+f"(c[3])
        : "r"(a[0]), "r"(a[1]), "r"(a[2]), "r"(a[3]), "r"(b[0]), "r"(b[1]));
}
__device__ __forceinline__ void cp16(uint32_t s, const void* g) {
    asm volatile("cp.async.cg.shared.global [%0], [%1], 16;" :: "r"(s), "l"(g));
}
#define CP_COMMIT() asm volatile("cp.async.commit_group;" ::: "memory")
#define CP_WAIT1()  asm volatile("cp.async.wait_group 1;"  ::: "memory")

__device__ __forceinline__ uint32_t pack_h(float x, float y) {
    __half2 h = __floats2half2_rn(x, y);
    return *reinterpret_cast<uint32_t*>(&h);
}

// smem tile geometry: 128 rows x 128B (64 fp16 K-chunk), XOR-16B swizzled,
// A|B per stage, 3 stages.
#define TILEB  16384
#define STAGEB (2 * TILEB)
#define NSTAGE 3
#define SM_SMEM (NSTAGE * STAGEB)   // 98304/CTA; 2 CTAs = 196608

// ---------------------------------------------------------------------------
// Batched fp32 -> fp16 conversions (y selects tensor)
// ---------------------------------------------------------------------------
__global__ __launch_bounds__(256)
void cvt3_hi(const float* __restrict__ s0, const float* __restrict__ s1,
             const float* __restrict__ s2, fp16* __restrict__ d0,
             fp16* __restrict__ d1, fp16* __restrict__ d2, int n4)
{
    int i = blockIdx.x * blockDim.x + threadIdx.x;
    if (i >= n4) return;
    const float* s = (blockIdx.y == 0) ? s0 : (blockIdx.y == 1) ? s1 : s2;
    fp16* d = (blockIdx.y == 0) ? d0 : (blockIdx.y == 1) ? d1 : d2;
    float4 v = reinterpret_cast<const float4*>(s)[i];
    reinterpret_cast<uint2*>(d)[i] = make_uint2(pack_h(v.x, v.y), pack_h(v.z, v.w));
}
__global__ __launch_bounds__(256)
void cvt4_hi(const float* __restrict__ s0, const float* __restrict__ s1,
             const float* __restrict__ s2, const float* __restrict__ s3,
             fp16* __restrict__ d0, fp16* __restrict__ d1,
             fp16* __restrict__ d2, fp16* __restrict__ d3, int n4)
{
    int i = blockIdx.x * blockDim.x + threadIdx.x;
    if (i >= n4) return;
    const float* s = (blockIdx.y == 0) ? s0 : (blockIdx.y == 1) ? s1
                   : (blockIdx.y == 2) ? s2 : s3;
    fp16* d = (blockIdx.y == 0) ? d0 : (blockIdx.y == 1) ? d1
            : (blockIdx.y == 2) ? d2 : d3;
    float4 v = reinterpret_cast<const float4*>(s)[i];
    reinterpret_cast<uint2*>(d)[i] = make_uint2(pack_h(v.x, v.y), pack_h(v.z, v.w));
}

// ---------------------------------------------------------------------------
// Single-pass fp16 HMMA NT GEMM. 128x128 CTA tile, 8 warps (4x2 grid, warp
// tile 32x64), K-chunk 64, cp.async 3-stage pipeline, 2 CTAs/SM.
// MODE 0: merged QKV projection. z=pp*8+h; pp=0: Q; pp=1: K (pad row scale);
//         pp=2: V transposed -> [BH,E,S].
// MODE 2: scores -> fp16 S (*1/16) into P buffer; 10 lower-triangular tiles
// MODE 3: attnv -> fp16 concat [B,S,H*E], K truncated at causal bound
// MODE 4: outproj -> fp32 d_out + bias
// ---------------------------------------------------------------------------
template <int MODE>
__global__ __launch_bounds__(256, 2)
void gemm_hf(const fp16* __restrict__ A0, const fp16* __restrict__ A1,
             const fp16* __restrict__ A2, const fp16* __restrict__ B0,
             const fp16* __restrict__ B1, const fp16* __restrict__ B2,
             void* __restrict__ O0, void* __restrict__ O1,
             void* __restrict__ O2,
             const float* __restrict__ pad, const float* __restrict__ bias)
{
    extern __shared__ char smem[];
    const uint32_t sb = smem_u32(smem);
    const int tid = threadIdx.x, wid = tid >> 5, lane = tid & 31;
    const int z = blockIdx.z;

    int m0, n0;
    if constexpr (MODE == 2) {
        const int mt_tab[10] = {0,1,1,2,2,2,3,3,3,3};
        const int nt_tab[10] = {0,0,1,0,1,2,0,1,2,3};
        m0 = mt_tab[blockIdx.x] * 128;
        n0 = nt_tab[blockIdx.x] * 128;
    } else {
        m0 = blockIdx.y * 128;
        n0 = blockIdx.x * 128;
    }

    int pp = 0, hh = 0;
    const fp16 *Ah, *Bh;
    int lda, ldb, nc;
    if constexpr (MODE == 0) {
        pp = z >> 3; hh = z & 7;
        const fp16* Ab = (pp == 0) ? A0 : (pp == 1) ? A1 : A2;
        const fp16* Bb = (pp == 0) ? B0 : (pp == 1) ? B1 : B2;
        Ah = Ab + (size_t)m0 * En;
        Bh = Bb + (size_t)hh * En * En + (size_t)n0 * En;
        lda = En; ldb = En; nc = En / 64;
    } else if constexpr (MODE == 2) {
        Ah = A0 + (size_t)z * Sn * En + (size_t)m0 * En;
        Bh = B0 + (size_t)z * Sn * En + (size_t)n0 * En;
        lda = En; ldb = En; nc = En / 64;
    } else if constexpr (MODE == 3) {
        Ah = A0 + (size_t)z * Sn * Sn + (size_t)m0 * Sn;
        Bh = B0 + (size_t)z * En * Sn + (size_t)n0 * Sn;
        lda = Sn; ldb = Sn; nc = (m0 + 128) / 64;   // causal truncation
    } else {
        Ah = A0 + (size_t)m0 * HEn;
        Bh = B0 + (size_t)n0 * HEn;
        lda = HEn; ldb = HEn; nc = HEn / 64;
    }

    auto issue = [&](int cc) {
        const uint32_t st = sb + (uint32_t)(cc % NSTAGE) * STAGEB;
        #pragma unroll
        for (int i = 0; i < 4; i++) {
            const int idx = i * 256 + tid;
            const int row = idx >> 3, ch = idx & 7;
            const uint32_t so = (uint32_t)((row << 7) + (((ch ^ (row & 7))) << 4));
            const size_t ga = (size_t)row * lda + (size_t)cc * 64 + ch * 8;
            const size_t gb = (size_t)row * ldb + (size_t)cc * 64 + ch * 8;
            cp16(st + so, Ah + ga);
            cp16(st + TILEB + so, Bh + gb);
        }
    };

    issue(0); CP_COMMIT();
    issue(1); CP_COMMIT();

    const int wm = wid & 3, wn = wid >> 2;
    const int arow = wm * 32 + (lane & 15);
    const int a7   = arow & 7;
    const int ac   = lane >> 4;
    const int brow = wn * 64 + (lane & 7);
    const int b7   = lane & 7;
    const int bc   = (lane >> 3) & 1;

    float c[2][8][4] = {};

    for (int cc = 0; cc < nc; ++cc) {
        CP_WAIT1();
        __syncthreads();
        if (cc + 2 < nc) issue(cc + 2);
        CP_COMMIT();

        const uint32_t st = sb + (uint32_t)(cc % NSTAGE) * STAGEB;
        #pragma unroll
        for (int kb = 0; kb < 4; kb++) {
            const uint32_t asw = (uint32_t)(((kb * 2 + ac) ^ a7) << 4);
            const uint32_t bsw = (uint32_t)(((kb * 2 + bc) ^ b7) << 4);
            uint32_t ah[2][4], bh[8][2];
            #pragma unroll
            for (int ma = 0; ma < 2; ma++)
                ldsm_x4(ah[ma], st + (uint32_t)((arow + ma * 16) << 7) + asw);
            #pragma unroll
            for (int na = 0; na < 8; na++)
                ldsm_x2(bh[na], st + TILEB + (uint32_t)((brow + na * 8) << 7) + bsw);
            #pragma unroll
            for (int ma = 0; ma < 2; ma++)
                #pragma unroll
                for (int na = 0; na < 8; na++)
                    mma_f16(c[ma][na], ah[ma], bh[na]);
        }
    }

    const int g = lane >> 2, tig = lane & 3;

    if (MODE == 0 && pp == 2) {
        // V projection: stage fp32 in smem, write transposed fp16 [BH,E,S]
        float* ts = reinterpret_cast<float*>(smem);
        __syncthreads();
        #pragma unroll
        for (int ma = 0; ma < 2; ma++) {
            const int rl = wm * 32 + ma * 16 + g;
            #pragma unroll
            for (int na = 0; na < 8; na++) {
                const int cl = wn * 64 + na * 8 + 2 * tig;
                ts[rl * 132 + cl]           = c[ma][na][0];
                ts[rl * 132 + cl + 1]       = c[ma][na][1];
                ts[(rl + 8) * 132 + cl]     = c[ma][na][2];
                ts[(rl + 8) * 132 + cl + 1] = c[ma][na][3];
            }
        }
        __syncthreads();
        fp16* Oh = (fp16*)O2;
        const int bb = m0 >> 9, sbase = m0 & 511;
        for (int i = tid; i < 128 * 64; i += 256) {
            const int d = i >> 6, s2 = (i & 63) * 2;
            float v0 = ts[s2 * 132 + d], v1 = ts[(s2 + 1) * 132 + d];
            size_t o = (((size_t)(bb * Hn + hh)) * En + n0 + d) * Sn + sbase + s2;
            *reinterpret_cast<uint32_t*>(Oh + o) = pack_h(v0, v1);
        }
        return;
    }

    #pragma unroll
    for (int ma = 0; ma < 2; ma++) {
        const int r0 = m0 + wm * 32 + ma * 16 + g;
        const int r1 = r0 + 8;
        float s0 = 1.0f, s1 = 1.0f;
        if constexpr (MODE == 0) {
            if (pp == 1) { s0 = pad[r0]; s1 = pad[r1]; }
        }
        #pragma unroll
        for (int na = 0; na < 8; na++) {
            const int cb = n0 + wn * 64 + na * 8 + 2 * tig;
            const float v0 = c[ma][na][0], v1 = c[ma][na][1];
            const float v2 = c[ma][na][2], v3 = c[ma][na][3];
            if constexpr (MODE == 0) {
                fp16* Oh = (fp16*)((pp == 0) ? O0 : O1);
                size_t o0 = (((size_t)((r0 >> 9) * Hn + hh)) * Sn + (r0 & 511)) * En + cb;
                size_t o1 = (((size_t)((r1 >> 9) * Hn + hh)) * Sn + (r1 & 511)) * En + cb;
                *reinterpret_cast<uint32_t*>(Oh + o0) = pack_h(v0 * s0, v1 * s0);
                *reinterpret_cast<uint32_t*>(Oh + o1) = pack_h(v2 * s1, v3 * s1);
            } else if constexpr (MODE == 2) {
                // fp16 S directly into the P buffer (softmax masks by index)
                fp16* Oh = (fp16*)O0;
                size_t o0 = (size_t)z * Sn * Sn + (size_t)r0 * Sn + cb;
                size_t o1 = (size_t)z * Sn * Sn + (size_t)r1 * Sn + cb;
                *reinterpret_cast<uint32_t*>(Oh + o0) = pack_h(v0 * 0.0625f, v1 * 0.0625f);
                *reinterpret_cast<uint32_t*>(Oh + o1) = pack_h(v2 * 0.0625f, v3 * 0.0625f);
            } else if constexpr (MODE == 3) {
                fp16* Oh = (fp16*)O0;
                size_t o0 = ((size_t)((z >> 3) * Sn + r0)) * HEn + (z & 7) * En + cb;
                size_t o1 = ((size_t)((z >> 3) * Sn + r1)) * HEn + (z & 7) * En + cb;
                *reinterpret_cast<uint32_t*>(Oh + o0) = pack_h(v0, v1);
                *reinterpret_cast<uint32_t*>(Oh + o1) = pack_h(v2, v3);
            } else {
                float* O = (float*)O0;
                const float bx = bias[cb], by = bias[cb + 1];
                float* p0 = O + (size_t)r0 * En + cb;
                float* p1 = O + (size_t)r1 * En + cb;
                *reinterpret_cast<float2*>(p0) = make_float2(v0 + bx, v1 + by);
                *reinterpret_cast<float2*>(p1) = make_float2(v2 + bx, v3 + by);
            }
        }
    }
}

// ---------------------------------------------------------------------------
// Warp-per-row causal softmax, IN PLACE on fp16 S/P buffer.
// 8 rows per 256-thread block; shuffle-only reductions; uint2 (4 fp16)
// per lane per 128-col group; touches only k < tend = ((q>>7)+1)*128.
// ---------------------------------------------------------------------------
__global__ __launch_bounds__(256)
void softmax_inplace(fp16* __restrict__ P)
{
    const int wid = threadIdx.x >> 5, lane = threadIdx.x & 31;
    const size_t row = (size_t)blockIdx.x * 8 + wid;
    const int q = (int)(row & (Sn - 1));
    uint2* p = reinterpret_cast<uint2*>(P + row * Sn);
    const int ng = (q >> 7) + 1;           // 1..4 groups of 128 cols

    float f[4][4];
    float m = -1e30f;
    #pragma unroll
    for (int gIdx = 0; gIdx < 4; gIdx++) {
        if (gIdx < ng) {
            uint2 x = p[gIdx * 32 + lane];
            const __half2* hp = reinterpret_cast<const __half2*>(&x);
            float2 a = __half22float2(hp[0]);
            float2 b = __half22float2(hp[1]);
            const int k = (gIdx * 32 + lane) * 4;
            f[gIdx][0] = (k + 0 <= q) ? a.x : -1e30f;
            f[gIdx][1] = (k + 1 <= q) ? a.y : -1e30f;
            f[gIdx][2] = (k + 2 <= q) ? b.x : -1e30f;
            f[gIdx][3] = (k + 3 <= q) ? b.y : -1e30f;
            m = fmaxf(m, fmaxf(fmaxf(f[gIdx][0], f[gIdx][1]),
                               fmaxf(f[gIdx][2], f[gIdx][3])));
        }
    }
    #pragma unroll
    for (int o = 16; o; o >>= 1) m = fmaxf(m, __shfl_xor_sync(0xffffffffu, m, o));

    float s = 0.0f;
    #pragma unroll
    for (int gIdx = 0; gIdx < 4; gIdx++) {
        if (gIdx < ng) {
            #pragma unroll
            for (int i = 0; i < 4; i++) {
                f[gIdx][i] = __expf(f[gIdx][i] - m);
                s += f[gIdx][i];
            }
        }
    }
    #pragma unroll
    for (int o = 16; o; o >>= 1) s += __shfl_xor_sync(0xffffffffu, s, o);
    const float inv = 1.0f / s;

    #pragma unroll
    for (int gIdx = 0; gIdx < 4; gIdx++) {
        if (gIdx < ng) {
            uint2 o;
            o.x = pack_h(f[gIdx][0] * inv, f[gIdx][1] * inv);
            o.y = pack_h(f[gIdx][2] * inv, f[gIdx][3] * inv);
            p[gIdx * 32 + lane] = o;
        }
    }
}

// ---------------------------------------------------------------------------
// Launch (my index 3 = scores GEMM — the launch ncu profiles)
// ---------------------------------------------------------------------------
extern "C" void kernel_launch(void* const* d_in, const int* in_sizes, int n_in,
                              void* d_out, int out_size)
{
    const float* q   = (const float*)d_in[0];
    const float* k   = (const float*)d_in[1];
    const float* v   = (const float*)d_in[2];
    const float* pad = (const float*)d_in[3];
    // d_in[4] = attn_mask (causal applied analytically)
    const float* Wq  = (const float*)d_in[5];
    const float* Wk  = (const float*)d_in[6];
    const float* Wv  = (const float*)d_in[7];
    const float* Wo  = (const float*)d_in[8];
    const float* bo  = (const float*)d_in[9];
    float* out = (float*)d_out;

    fp16 *qh, *kh, *vh, *Wqh, *Wkh, *Wvh, *Woh;
    fp16 *Qh, *Kh, *Vth, *Ph, *Ch;
    cudaGetSymbolAddress((void**)&qh,  g_qh);
    cudaGetSymbolAddress((void**)&kh,  g_kh);
    cudaGetSymbolAddress((void**)&vh,  g_vh);
    cudaGetSymbolAddress((void**)&Wqh, g_Wqh);
    cudaGetSymbolAddress((void**)&Wkh, g_Wkh);
    cudaGetSymbolAddress((void**)&Wvh, g_Wvh);
    cudaGetSymbolAddress((void**)&Woh, g_Woh);
    cudaGetSymbolAddress((void**)&Qh,  g_Qh);
    cudaGetSymbolAddress((void**)&Kh,  g_Kh);
    cudaGetSymbolAddress((void**)&Vth, g_Vth);
    cudaGetSymbolAddress((void**)&Ph,  g_Ph);
    cudaGetSymbolAddress((void**)&Ch,  g_Ch);

    cudaFuncSetAttribute((const void*)gemm_hf<0>, cudaFuncAttributeMaxDynamicSharedMemorySize, SM_SMEM);
    cudaFuncSetAttribute((const void*)gemm_hf<2>, cudaFuncAttributeMaxDynamicSharedMemorySize, SM_SMEM);
    cudaFuncSetAttribute((const void*)gemm_hf<3>, cudaFuncAttributeMaxDynamicSharedMemorySize, SM_SMEM);
    cudaFuncSetAttribute((const void*)gemm_hf<4>, cudaFuncAttributeMaxDynamicSharedMemorySize, SM_SMEM);

    const int n4x = Mn * En / 4;          // 1048576
    const int n4w = Hn * En * En / 4;     // 131072 (== En*HEn/4 for Wo)

    // index 0-1: batched conversions
    cvt3_hi<<<dim3(n4x / 256, 3), 256>>>(q, k, v, qh, kh, vh, n4x);
    cvt4_hi<<<dim3(n4w / 256, 4), 256>>>(Wq, Wk, Wv, Wo, Wqh, Wkh, Wvh, Woh, n4w);

    // index 2: merged QKV projections, grid (2,128,24)
    gemm_hf<0><<<dim3(2, 128, 24), 256, SM_SMEM>>>(
        qh, kh, vh, Wqh, Wkh, Wvh, Qh, Kh, Vth, pad, nullptr);

    // index 3 (profiled): scores -> fp16 into P buffer, 10 tiles x 256 bh
    gemm_hf<2><<<dim3(10, 1, 256), 256, SM_SMEM>>>(
        Qh, nullptr, nullptr, Kh, nullptr, nullptr, Ph, nullptr, nullptr,
        nullptr, nullptr);

    // in-place warp-per-row softmax: 131072 rows / 8 per block
    softmax_inplace<<<BHn * Sn / 8, 256>>>(Ph);

    // attn @ V: (2,4,256), K truncated at causal boundary
    gemm_hf<3><<<dim3(2, 4, 256), 256, SM_SMEM>>>(
        Ph, nullptr, nullptr, Vth, nullptr, nullptr, Ch, nullptr, nullptr,
        nullptr, nullptr);

    // out projection: (2,128)
    gemm_hf<4><<<dim3(2, 128, 1), 256, SM_SMEM>>>(
        Ch, nullptr, nullptr, Woh, nullptr, nullptr, out, nullptr, nullptr,
        nullptr, bo);
}